// round 4
// baseline (speedup 1.0000x reference)
#include <cuda_runtime.h>
#include <math.h>

#define LL 512
#define BB 128
#define DD 512
#define TT 200
#define EE 384
#define CC 128
#define HH 512
#define VV 46
#define G4H 2048
#define NBLK 128

typedef unsigned long long ull;

// ---------------- device scratch ----------------
__device__ __align__(128) float g_keyfT[BB * CC * LL];  // [b][c][l]
__device__ __align__(128) float g_valf[BB * LL * CC];   // [b][l][c]
__device__ __align__(128) float g_embW[VV * G4H];
__device__ __align__(128) float g_bias1[G4H];
__device__ __align__(128) float g_bias2[G4H];
__device__ __align__(128) float g_h0T[2][HH * BB];
__device__ __align__(128) float g_h1T[2][HH * BB];
__device__ __align__(128) float g_h2T[2][HH * BB];
__device__ __align__(128) float g_h2n[BB * HH];
__device__ __align__(128) float g_ctxT[CC * BB];
__device__ __align__(128) float g_phiT[HH * CC];        // [k][c]
__device__ int   g_tok[TT * BB];
__device__ unsigned g_barctr;

__device__ __forceinline__ float sigmoidf_(float x) { return 1.f / (1.f + expf(-x)); }

__device__ __forceinline__ ull pack2(float lo, float hi) {
    ull r; asm("mov.b64 %0, {%1, %2};" : "=l"(r) : "f"(lo), "f"(hi)); return r;
}
__device__ __forceinline__ float2 unpack2(ull v) {
    float2 r; asm("mov.b64 {%0, %1}, %2;" : "=f"(r.x), "=f"(r.y) : "l"(v)); return r;
}
__device__ __forceinline__ void fma2(ull& d, ull a, ull b) {
    asm("fma.rn.f32x2 %0, %1, %2, %0;" : "+l"(d) : "l"(a), "l"(b));
}

// ---------------- grid barrier ----------------
__device__ __forceinline__ void gbar(unsigned& tgt) {
    __threadfence();
    __syncthreads();
    if (threadIdx.x == 0) {
        atomicAdd(&g_barctr, 1u);
        unsigned v;
        do {
            asm volatile("ld.acquire.gpu.u32 %0, [%1];" : "=r"(v) : "l"(&g_barctr) : "memory");
        } while (v < tgt);
    }
    __syncthreads();
    tgt += NBLK;
}

// ---------------- cp.async helper ----------------
__device__ __forceinline__ void cp_cg16(float* dst, const float* src) {
    unsigned d = (unsigned)__cvta_generic_to_shared(dst);
    asm volatile("cp.async.cg.shared.global [%0], [%1], 16;" :: "r"(d), "l"(src) : "memory");
}

// ---------------- LSTM GEMM: per-warp K-slice ----------------
__device__ __forceinline__ void lstm_prefetch(float* xb, int buf, int kc, int KA,
    const float* xaT, const float* hT, int lane)
{
    const float* s = (kc < KA) ? (xaT + (size_t)kc * 128) : (hT + (size_t)(kc - KA) * 128);
    float* d = xb + buf * 2048 + lane * 4;
    const float* sp = s + lane * 4;
#pragma unroll
    for (int r = 0; r < 16; r++)
        cp_cg16(d + r * 128, sp + r * 128);
    asm volatile("cp.async.commit_group;" ::: "memory");
}

__device__ __forceinline__ void lstm_compute_chunk(ull acc[4][8], const float* X,
    int kc, int KA, const float* wa, int waStride, int waOff, const float* whh,
    int jr0, int bg)
{
#pragma unroll
    for (int kq = 0; kq < 4; kq++) {
        const int kg = kc + kq * 4;
        float4 wv[4];
#pragma unroll
        for (int c = 0; c < 4; c++) {
            const float* wr = (kg < KA)
                ? (wa + (size_t)(jr0 + c) * waStride + waOff + kg)
                : (whh + (size_t)(jr0 + c) * 512 + (kg - KA));
            wv[c] = __ldg(reinterpret_cast<const float4*>(wr));
        }
#pragma unroll
        for (int kk = 0; kk < 4; kk++) {
            const float* xr = X + (kq * 4 + kk) * 128 + (bg << 4);
            ulonglong2 u0 = *reinterpret_cast<const ulonglong2*>(xr + 0);
            ulonglong2 u1 = *reinterpret_cast<const ulonglong2*>(xr + 4);
            ulonglong2 u2 = *reinterpret_cast<const ulonglong2*>(xr + 8);
            ulonglong2 u3 = *reinterpret_cast<const ulonglong2*>(xr + 12);
#pragma unroll
            for (int c = 0; c < 4; c++) {
                const float wc = (kk == 0) ? wv[c].x : (kk == 1) ? wv[c].y : (kk == 2) ? wv[c].z : wv[c].w;
                const ull w2 = pack2(wc, wc);
                fma2(acc[c][0], u0.x, w2); fma2(acc[c][1], u0.y, w2);
                fma2(acc[c][2], u1.x, w2); fma2(acc[c][3], u1.y, w2);
                fma2(acc[c][4], u2.x, w2); fma2(acc[c][5], u2.y, w2);
                fma2(acc[c][6], u3.x, w2); fma2(acc[c][7], u3.y, w2);
            }
        }
    }
}

__device__ void lstm_phase2(float* stage, float* csm, int hhbase,
    const float* xaT, const float* hT, int KA, int K,
    const float* wa, int waStride, int waOff, const float* whh,
    const float* pre, const int* tokp,
    float* hoT, float* hN)
{
    const int tid = threadIdx.x;
    const int w = tid >> 5, lane = tid & 31;
    const int cg = lane >> 3, bg = lane & 7;
    const int jr0 = (cg << 9) + hhbase;
    float* xb = stage + (w << 12);
    const int KW = K >> 3;
    const int NCH = KW >> 4;
    const int k0w = w * KW;

    ull acc[4][8];
#pragma unroll
    for (int c = 0; c < 4; c++)
#pragma unroll
        for (int j = 0; j < 8; j++) acc[c][j] = 0ull;

    lstm_prefetch(xb, 0, k0w, KA, xaT, hT, lane);
    lstm_prefetch(xb, 1, k0w + 16, KA, xaT, hT, lane);
    for (int c = 0; c < NCH; c++) {
        if (c + 1 < NCH) asm volatile("cp.async.wait_group 1;" ::: "memory");
        else             asm volatile("cp.async.wait_group 0;" ::: "memory");
        __syncwarp();
        lstm_compute_chunk(acc, xb + (c & 1) * 2048, k0w + c * 16, KA,
                           wa, waStride, waOff, whh, jr0, bg);
        if (c + 2 < NCH) lstm_prefetch(xb, c & 1, k0w + (c + 2) * 16, KA, xaT, hT, lane);
    }
    __syncwarp();

    // write partials into this warp's buffer 0
#pragma unroll
    for (int c = 0; c < 4; c++)
#pragma unroll
        for (int j = 0; j < 8; j++) {
            float2 v = unpack2(acc[c][j]);
            *reinterpret_cast<float2*>(xb + (cg * 4 + c) * 128 + (bg << 4) + j * 2) = v;
        }
    __syncthreads();

    // fused reduce + bias + cell nonlinearity (2 cells per thread)
#pragma unroll
    for (int cell = tid; cell < 512; cell += 256) {
        const int hh = cell >> 7, b = cell & 127;
        const int pbase = tokp ? (tokp[b] * G4H) : 0;
        float g4[4];
#pragma unroll
        for (int g = 0; g < 4; g++) {
            float s = pre[pbase + (g << 9) + hhbase + hh];
            const int off = (g * 4 + hh) * 128 + b;
#pragma unroll
            for (int ww = 0; ww < 8; ww++) s += stage[(ww << 12) + off];
            g4[g] = s;
        }
        const float cn = sigmoidf_(g4[1]) * csm[cell] + sigmoidf_(g4[0]) * tanhf(g4[2]);
        const float h = sigmoidf_(g4[3]) * tanhf(cn);
        csm[cell] = cn;
        hoT[(size_t)(hhbase + hh) * 128 + b] = h;
        if (hN) hN[(size_t)b * 512 + hhbase + hh] = h;
    }
}

// ---------------- attention + output projection (block = batch row) ----------------
__device__ void attn_phase2(float* sm, int b, const int* lens, const float* phi_b,
    const float* out_w, const float* out_b,
    float* attn_out, float* logits_out)
{
    float* h2s  = sm;            // 512
    float* qs   = sm + 512;      // 128
    float* qp   = sm + 640;      // 1024
    float* as   = sm + 1664;     // 512
    float* ctxp = sm + 2176;     // 1024
    float* ctxs = sm + 3200;     // 128
    float* red  = sm + 3328;     // 256

    const int tid = threadIdx.x;
    const int warp = tid >> 5, lane = tid & 31;

    h2s[tid]       = __ldcg(&g_h2n[(size_t)b * 512 + tid]);
    h2s[tid + 256] = __ldcg(&g_h2n[(size_t)b * 512 + tid + 256]);
    __syncthreads();

    // q partials
    {
        float4 acc = make_float4(0.f, 0.f, 0.f, 0.f);
        for (int kk = 0; kk < 64; kk++) {
            int k = warp * 64 + kk;
            float hv = h2s[k];
            float4 pv = *reinterpret_cast<const float4*>(&g_phiT[(k << 7) + lane * 4]);
            acc.x = fmaf(hv, pv.x, acc.x); acc.y = fmaf(hv, pv.y, acc.y);
            acc.z = fmaf(hv, pv.z, acc.z); acc.w = fmaf(hv, pv.w, acc.w);
        }
        *reinterpret_cast<float4*>(&qp[warp * 128 + lane * 4]) = acc;
    }
    __syncthreads();
    if (tid < 128) {
        float q = phi_b[tid];
#pragma unroll
        for (int w = 0; w < 8; w++) q += qp[w * 128 + tid];
        qs[tid] = q;
    }
    __syncthreads();

    // energies
    {
        int half = tid >> 7, tl = tid & 127, l0 = tl * 4;
        float e0 = 0.f, e1 = 0.f, e2 = 0.f, e3 = 0.f;
        const float* kf = g_keyfT + ((size_t)b << 16) + l0;
        int c0 = half * 64;
#pragma unroll 4
        for (int c = c0; c < c0 + 64; c++) {
            float4 kv = __ldcg(reinterpret_cast<const float4*>(kf + ((size_t)c << 9)));
            float q = qs[c];
            e0 = fmaf(kv.x, q, e0); e1 = fmaf(kv.y, q, e1);
            e2 = fmaf(kv.z, q, e2); e3 = fmaf(kv.w, q, e3);
        }
        __syncthreads();
        *reinterpret_cast<float4*>(&qp[half * 512 + l0]) = make_float4(e0, e1, e2, e3);
    }
    __syncthreads();

    float e0 = qp[tid]       + qp[512 + tid];
    float e1 = qp[tid + 256] + qp[512 + tid + 256];

    red[tid] = fmaxf(e0, e1);
    __syncthreads();
    for (int s = 128; s > 0; s >>= 1) {
        if (tid < s) red[tid] = fmaxf(red[tid], red[tid + s]);
        __syncthreads();
    }
    const float mx = red[0];
    __syncthreads();

    const int len = lens[b];
    float p0 = (tid < len)       ? expf(e0 - mx) : 0.f;
    float p1 = (tid + 256 < len) ? expf(e1 - mx) : 0.f;
    red[tid] = p0 + p1;
    __syncthreads();
    for (int s = 128; s > 0; s >>= 1) {
        if (tid < s) red[tid] += red[tid + s];
        __syncthreads();
    }
    const float inv = 1.f / fmaxf(red[0], 1e-12f);
    __syncthreads();

    float av0 = p0 * inv, av1 = p1 * inv;
    as[tid] = av0; as[tid + 256] = av1;
    if (attn_out) {
        attn_out[(size_t)b * LL + tid]       = av0;
        attn_out[(size_t)b * LL + tid + 256] = av1;
    }
    __syncthreads();

    // ctx partials
    {
        float c0v = 0.f, c1v = 0.f, c2v = 0.f, c3v = 0.f;
        const float* vf = g_valf + ((size_t)b << 16) + lane * 4;
        for (int i = 0; i < 64; i++) {
            int l = warp * 64 + i;
            float4 vv = __ldcg(reinterpret_cast<const float4*>(vf + ((size_t)l << 7)));
            float av = as[l];
            c0v = fmaf(vv.x, av, c0v); c1v = fmaf(vv.y, av, c1v);
            c2v = fmaf(vv.z, av, c2v); c3v = fmaf(vv.w, av, c3v);
        }
        *reinterpret_cast<float4*>(&ctxp[warp * 128 + lane * 4]) = make_float4(c0v, c1v, c2v, c3v);
    }
    __syncthreads();
    if (tid < 128) {
        float c = 0.f;
#pragma unroll
        for (int w = 0; w < 8; w++) c += ctxp[w * 128 + tid];
        ctxs[tid] = c;
        g_ctxT[tid * 128 + b] = c;
    }
    __syncthreads();

    if (logits_out) {
        for (int v = warp; v < VV; v += 8) {
            const float* wr = out_w + (size_t)v * (HH + CC);
            float acc = 0.f;
#pragma unroll
            for (int it = 0; it < 5; it++) {
                int k0 = it * 128 + lane * 4;
                float4 wv = *reinterpret_cast<const float4*>(&wr[k0]);
                float4 xv = (it < 4) ? *reinterpret_cast<const float4*>(&h2s[k0])
                                     : *reinterpret_cast<const float4*>(&ctxs[k0 - 512]);
                acc = fmaf(wv.x, xv.x, acc); acc = fmaf(wv.y, xv.y, acc);
                acc = fmaf(wv.z, xv.z, acc); acc = fmaf(wv.w, xv.w, acc);
            }
#pragma unroll
            for (int off = 16; off > 0; off >>= 1)
                acc += __shfl_xor_sync(0xFFFFFFFF, acc, off);
            if (lane == 0) logits_out[(size_t)b * VV + v] = acc + out_b[v];
        }
    }
}

// ---------------- persistent kernel ----------------
__global__ void __launch_bounds__(256, 1) speller_persistent(
    const float* __restrict__ wih0, const float* __restrict__ whh0,
    const float* __restrict__ wih1, const float* __restrict__ whh1,
    const float* __restrict__ wih2, const float* __restrict__ whh2,
    const int* __restrict__ lens, const float* __restrict__ phi_b,
    const float* __restrict__ out_w, const float* __restrict__ out_b,
    const float* __restrict__ cx0, const float* __restrict__ cx1,
    const float* __restrict__ cx2,
    float* __restrict__ attn_base, float* __restrict__ logits_base)
{
    extern __shared__ float smem[];
    float* stage = smem;            // 8 warps * 4096 floats = 128 KB
    float* csm   = smem + 32768;    // 3 * 512 floats = 6 KB

    const int bk = blockIdx.x;
    const int hhbase = bk * 4;
    const int tid = threadIdx.x;
    unsigned tgt = NBLK;

    for (int cell = tid; cell < 512; cell += 256) {
        int hh = cell >> 7;
        csm[cell]        = cx0[hhbase + hh];
        csm[512 + cell]  = cx1[hhbase + hh];
        csm[1024 + cell] = cx2[hhbase + hh];
    }
    __syncthreads();

    // initial context from initial decoder state
    attn_phase2(stage, bk, lens, phi_b, out_w, out_b, nullptr, nullptr);
    gbar(tgt);

    for (int t = 0; t < TT; t++) {
        const int p = t & 1;
        lstm_phase2(stage, csm, hhbase,
                    g_ctxT, g_h0T[p], 128, 640,
                    wih0, EE + CC, EE, whh0,
                    g_embW, g_tok + (size_t)t * BB,
                    g_h0T[p ^ 1], nullptr);
        gbar(tgt);
        lstm_phase2(stage, csm + 512, hhbase,
                    g_h0T[p ^ 1], g_h1T[p], 512, 1024,
                    wih1, 512, 0, whh1,
                    g_bias1, nullptr,
                    g_h1T[p ^ 1], nullptr);
        gbar(tgt);
        lstm_phase2(stage, csm + 1024, hhbase,
                    g_h1T[p ^ 1], g_h2T[p], 512, 1024,
                    wih2, 512, 0, whh2,
                    g_bias2, nullptr,
                    g_h2T[p ^ 1], g_h2n);
        gbar(tgt);
        attn_phase2(stage, bk, lens, phi_b, out_w, out_b,
                    attn_base + (size_t)t * BB * LL,
                    logits_base + (size_t)t * BB * VV);
        gbar(tgt);
    }
}

// ---------------- precompute: keyf(T)/valf ----------------
__global__ void __launch_bounds__(256) keyval_kernel(
    const float* __restrict__ lf,
    const float* __restrict__ key_w, const float* __restrict__ key_b,
    const float* __restrict__ value_w, const float* __restrict__ value_b)
{
    __shared__ __align__(16) float As[16][64];
    __shared__ __align__(16) float Bs[16][64];

    const int tid = threadIdx.x;
    const int m0 = blockIdx.x * 64;
    const int n0 = blockIdx.y * 64;
    const int ty = tid >> 4;
    const int tx = tid & 15;

    float acc[4][4];
#pragma unroll
    for (int i = 0; i < 4; i++)
#pragma unroll
        for (int j = 0; j < 4; j++) acc[i][j] = 0.f;

    const int mi = tid >> 2;
    const int kq = (tid & 3) * 4;

    for (int kb = 0; kb < DD; kb += 16) {
        {
            float4 v = *reinterpret_cast<const float4*>(&lf[(size_t)(m0 + mi) * DD + kb + kq]);
            As[kq + 0][mi] = v.x; As[kq + 1][mi] = v.y; As[kq + 2][mi] = v.z; As[kq + 3][mi] = v.w;
        }
        {
            int n = n0 + mi;
            const float* wrow = (n < CC) ? (key_w + (size_t)n * DD) : (value_w + (size_t)(n - CC) * DD);
            float4 v = *reinterpret_cast<const float4*>(&wrow[kb + kq]);
            Bs[kq + 0][mi] = v.x; Bs[kq + 1][mi] = v.y; Bs[kq + 2][mi] = v.z; Bs[kq + 3][mi] = v.w;
        }
        __syncthreads();
#pragma unroll
        for (int k = 0; k < 16; k++) {
            float4 av = *reinterpret_cast<const float4*>(&As[k][ty * 4]);
            float4 bv = *reinterpret_cast<const float4*>(&Bs[k][tx * 4]);
            float aa[4] = {av.x, av.y, av.z, av.w};
            float bb[4] = {bv.x, bv.y, bv.z, bv.w};
#pragma unroll
            for (int i = 0; i < 4; i++)
#pragma unroll
                for (int j = 0; j < 4; j++) acc[i][j] = fmaf(aa[i], bb[j], acc[i][j]);
        }
        __syncthreads();
    }

#pragma unroll
    for (int i = 0; i < 4; i++) {
        int m = m0 + ty * 4 + i;
        int l = m >> 7, b = m & 127;
#pragma unroll
        for (int j = 0; j < 4; j++) {
            int n = n0 + tx * 4 + j;
            if (n < CC)
                g_keyfT[((size_t)b << 16) + (size_t)n * 512 + l] = acc[i][j] + key_b[n];
            else
                g_valf[((size_t)b << 16) + (size_t)l * CC + (n - CC)] = acc[i][j] + value_b[n - CC];
        }
    }
}

// ---------------- precompute: embW ----------------
__global__ void __launch_bounds__(256) embw_kernel(
    const float* __restrict__ emb, const float* __restrict__ w_ih0,
    const float* __restrict__ b_ih0, const float* __restrict__ b_hh0)
{
    __shared__ float es[EE];
    const int v = blockIdx.x, tid = threadIdx.x;
    for (int i = tid; i < EE; i += 256) es[i] = emb[(size_t)v * EE + i];
    __syncthreads();
    for (int j = tid; j < G4H; j += 256) {
        const float* wr = w_ih0 + (size_t)j * (EE + CC);
        float a0 = b_ih0[j] + b_hh0[j], a1 = 0.f, a2 = 0.f, a3 = 0.f;
        for (int e = 0; e < EE; e += 4) {
            a0 = fmaf(es[e + 0], wr[e + 0], a0);
            a1 = fmaf(es[e + 1], wr[e + 1], a1);
            a2 = fmaf(es[e + 2], wr[e + 2], a2);
            a3 = fmaf(es[e + 3], wr[e + 3], a3);
        }
        g_embW[(size_t)v * G4H + j] = a0 + a1 + a2 + a3;
    }
}

// ---------------- precompute: misc (fused) ----------------
__global__ void __launch_bounds__(256) misc_kernel(
    const float* __restrict__ bi1, const float* __restrict__ bh1,
    const float* __restrict__ bi2, const float* __restrict__ bh2,
    const float* __restrict__ phi_w, const int* __restrict__ transcript,
    const float* __restrict__ hx0, const float* __restrict__ hx1,
    const float* __restrict__ hx2)
{
    int i = blockIdx.x * 256 + threadIdx.x;
    if (i == 0) g_barctr = 0;
    if (i < G4H) { g_bias1[i] = bi1[i] + bh1[i]; g_bias2[i] = bi2[i] + bh2[i]; }
    if (i < HH * CC) {
        int k = i >> 7, c = i & 127;
        g_phiT[i] = phi_w[(size_t)c * HH + k];
    }
    if (i < TT * BB) {
        int t = i / BB, b = i % BB;
        g_tok[i] = (t == 0) ? 0 : transcript[(size_t)(t - 1) * BB + b];
    }
    if (i < HH * BB) {
        int k = i >> 7, b = i & 127;
        g_h0T[0][i] = hx0[k];
        g_h1T[0][i] = hx1[k];
        g_h2T[0][i] = hx2[k];
        g_h2n[(size_t)b * HH + k] = hx2[k];
    }
}

// ---------------- launch ----------------
extern "C" void kernel_launch(void* const* d_in, const int* in_sizes, int n_in,
                              void* d_out, int out_size)
{
    const float* lf         = (const float*)d_in[0];
    const int*   lens       = (const int*)  d_in[1];
    const int*   transcript = (const int*)  d_in[2];
    const float* emb        = (const float*)d_in[3];
    const float* w_ih0 = (const float*)d_in[4];
    const float* w_hh0 = (const float*)d_in[5];
    const float* b_ih0 = (const float*)d_in[6];
    const float* b_hh0 = (const float*)d_in[7];
    const float* w_ih1 = (const float*)d_in[8];
    const float* w_hh1 = (const float*)d_in[9];
    const float* b_ih1 = (const float*)d_in[10];
    const float* b_hh1 = (const float*)d_in[11];
    const float* w_ih2 = (const float*)d_in[12];
    const float* w_hh2 = (const float*)d_in[13];
    const float* b_ih2 = (const float*)d_in[14];
    const float* b_hh2 = (const float*)d_in[15];
    const float* phi_w = (const float*)d_in[16];
    const float* phi_b = (const float*)d_in[17];
    const float* key_w = (const float*)d_in[18];
    const float* key_b = (const float*)d_in[19];
    const float* value_w = (const float*)d_in[20];
    const float* value_b = (const float*)d_in[21];
    const float* out_w = (const float*)d_in[22];
    const float* out_b = (const float*)d_in[23];
    const float* hx0 = (const float*)d_in[24];
    const float* cx0 = (const float*)d_in[25];
    const float* hx1 = (const float*)d_in[26];
    const float* cx1 = (const float*)d_in[27];
    const float* hx2 = (const float*)d_in[28];
    const float* cx2 = (const float*)d_in[29];

    float* out = (float*)d_out;
    float* logits_base = out;                        // [T,B,V]
    float* attn_base   = out + (size_t)TT * BB * VV; // [T,B,L]

    const int smem_bytes = (32768 + 1536) * 4;
    cudaFuncSetAttribute(speller_persistent,
                         cudaFuncAttributeMaxDynamicSharedMemorySize, smem_bytes);

    keyval_kernel<<<dim3(1024, 4), 256>>>(lf, key_w, key_b, value_w, value_b);
    embw_kernel<<<VV, 256>>>(emb, w_ih0, b_ih0, b_hh0);
    misc_kernel<<<256, 256>>>(b_ih1, b_hh1, b_ih2, b_hh2, phi_w, transcript,
                              hx0, hx1, hx2);
    speller_persistent<<<NBLK, 256, smem_bytes>>>(
        w_ih0, w_hh0, w_ih1, w_hh1, w_ih2, w_hh2,
        lens, phi_b, out_w, out_b, cx0, cx1, cx2,
        attn_base, logits_base);
}

// round 5
// speedup vs baseline: 1.0228x; 1.0228x over previous
#include <cuda_runtime.h>
#include <math.h>

#define LL 512
#define BB 128
#define DD 512
#define TT 200
#define EE 384
#define CC 128
#define HH 512
#define VV 46
#define G4H 2048
#define NBLK 128

typedef unsigned long long ull;

// ---------------- device scratch ----------------
__device__ __align__(128) float g_keyfT[BB * CC * LL];  // [b][c][l]
__device__ __align__(128) float g_valf[BB * LL * CC];   // [b][l][c]
__device__ __align__(128) float g_embW[VV * G4H];
__device__ __align__(128) float g_bias1[G4H];
__device__ __align__(128) float g_bias2[G4H];
__device__ __align__(128) float g_h0T[2][HH * BB];      // [k][b] fp32
__device__ __align__(128) float g_h1T[2][HH * BB];
__device__ __align__(128) float g_h2T[2][HH * BB];
__device__ __align__(128) float g_h2n[BB * HH];         // [b][k] for attention
__device__ __align__(128) float g_ctxT[CC * BB];        // [c][b]
__device__ __align__(128) float g_phiT[HH * CC];        // [k][c]
// pre-split tf32 hi/lo weights, per-block contiguous: [blk][k][16 cols][2]
__device__ __align__(128) float g_w0hl[NBLK * 640 * 16 * 2];   // L0: ctx(128)+h(512)
__device__ __align__(128) float g_w1hl[NBLK * 1024 * 16 * 2];  // L1: h0(512)+h1(512)
__device__ __align__(128) float g_w2hl[NBLK * 1024 * 16 * 2];  // L2
__device__ int   g_tok[TT * BB];
__device__ unsigned g_barctr;

__device__ __forceinline__ float sigmoidf_(float x) { return 1.f / (1.f + expf(-x)); }

// tf32 split: x = hi + lo (hi,lo tf32-representable), error ~2^-24
__device__ __forceinline__ void tsplit(float x, unsigned& h, unsigned& l) {
    asm("cvt.rna.tf32.f32 %0, %1;" : "=r"(h) : "f"(x));
    float r = x - __uint_as_float(h);
    asm("cvt.rna.tf32.f32 %0, %1;" : "=r"(l) : "f"(r));
}

__device__ __forceinline__ void mma8(float c[4],
    unsigned a0, unsigned a1, unsigned a2, unsigned a3,
    unsigned b0, unsigned b1)
{
    asm volatile("mma.sync.aligned.m16n8k8.row.col.f32.tf32.tf32.f32 "
        "{%0,%1,%2,%3}, {%4,%5,%6,%7}, {%8,%9}, {%0,%1,%2,%3};"
        : "+f"(c[0]), "+f"(c[1]), "+f"(c[2]), "+f"(c[3])
        : "r"(a0), "r"(a1), "r"(a2), "r"(a3), "r"(b0), "r"(b1));
}

// ---------------- grid barrier ----------------
__device__ __forceinline__ void gbar(unsigned& tgt) {
    __threadfence();
    __syncthreads();
    if (threadIdx.x == 0) {
        atomicAdd(&g_barctr, 1u);
        unsigned v;
        do {
            asm volatile("ld.acquire.gpu.u32 %0, [%1];" : "=r"(v) : "l"(&g_barctr) : "memory");
        } while (v < tgt);
    }
    __syncthreads();
    tgt += NBLK;
}

// ---------------- mma span: accumulate nk8 k-chunks from one activation array ----------------
// A = W slice (16 cols, hi/lo interleaved float2, per-block contiguous)
// B = X (fp32 k-major [k][128 batches]), split to tf32 hi/lo in registers
__device__ __forceinline__ void mma_span(float c0[4], float c1[4],
    const float2* __restrict__ wp, const float* __restrict__ xp, int nk8,
    int bq, int kq, int b0)
{
#pragma unroll 4
    for (int k8 = 0; k8 < nk8; k8++) {
        const int kb = k8 * 8;
        float2 A0 = __ldg(wp + (kb + kq) * 16 + bq);
        float2 A1 = __ldg(wp + (kb + kq) * 16 + bq + 8);
        float2 A2 = __ldg(wp + (kb + kq + 4) * 16 + bq);
        float2 A3 = __ldg(wp + (kb + kq + 4) * 16 + bq + 8);
        float x00 = __ldcg(xp + (size_t)(kb + kq) * 128 + b0 + bq);
        float x01 = __ldcg(xp + (size_t)(kb + kq + 4) * 128 + b0 + bq);
        float x10 = __ldcg(xp + (size_t)(kb + kq) * 128 + b0 + 8 + bq);
        float x11 = __ldcg(xp + (size_t)(kb + kq + 4) * 128 + b0 + 8 + bq);

        unsigned bh00, bl00, bh01, bl01, bh10, bl10, bh11, bl11;
        tsplit(x00, bh00, bl00); tsplit(x01, bh01, bl01);
        tsplit(x10, bh10, bl10); tsplit(x11, bh11, bl11);

        const unsigned ah0 = __float_as_uint(A0.x), al0 = __float_as_uint(A0.y);
        const unsigned ah1 = __float_as_uint(A1.x), al1 = __float_as_uint(A1.y);
        const unsigned ah2 = __float_as_uint(A2.x), al2 = __float_as_uint(A2.y);
        const unsigned ah3 = __float_as_uint(A3.x), al3 = __float_as_uint(A3.y);

        // tile 0 (batches b0..b0+7): hi*hi + hi*lo + lo*hi
        mma8(c0, ah0, ah1, ah2, ah3, bh00, bh01);
        mma8(c0, ah0, ah1, ah2, ah3, bl00, bl01);
        mma8(c0, al0, al1, al2, al3, bh00, bh01);
        // tile 1 (batches b0+8..b0+15)
        mma8(c1, ah0, ah1, ah2, ah3, bh10, bh11);
        mma8(c1, ah0, ah1, ah2, ah3, bl10, bl11);
        mma8(c1, al0, al1, al2, al3, bh10, bh11);
    }
}

// ---------------- LSTM phase (tensor-core) ----------------
__device__ void lstm_phase3(float* Gs, float* csm, int hhbase,
    const float* xa, int nka8, const float* xh, int nkh8,
    const float* whl_blk, const float* pre, const int* tokp,
    float* hoT, float* hN)
{
    const int tid = threadIdx.x;
    const int w = tid >> 5, lane = tid & 31;
    const int bq = lane >> 2, kq = lane & 3;
    const int b0 = w * 16;

    float c0[4] = {0.f, 0.f, 0.f, 0.f};
    float c1[4] = {0.f, 0.f, 0.f, 0.f};
    const float2* wp = (const float2*)whl_blk;

    mma_span(c0, c1, wp, xa, nka8, bq, kq, b0);
    mma_span(c0, c1, wp + (size_t)nka8 * 8 * 16, xh, nkh8, bq, kq, b0);

    // C fragment -> Gs[16 cols][128 batches]
    Gs[bq * 128 + b0 + 2 * kq]           = c0[0];
    Gs[bq * 128 + b0 + 2 * kq + 1]       = c0[1];
    Gs[(bq + 8) * 128 + b0 + 2 * kq]     = c0[2];
    Gs[(bq + 8) * 128 + b0 + 2 * kq + 1] = c0[3];
    Gs[bq * 128 + b0 + 8 + 2 * kq]           = c1[0];
    Gs[bq * 128 + b0 + 8 + 2 * kq + 1]       = c1[1];
    Gs[(bq + 8) * 128 + b0 + 8 + 2 * kq]     = c1[2];
    Gs[(bq + 8) * 128 + b0 + 8 + 2 * kq + 1] = c1[3];
    __syncthreads();

    // fused bias + nonlinearity (2 cells per thread)
#pragma unroll
    for (int cell = tid; cell < 512; cell += 256) {
        const int hh = cell >> 7, b = cell & 127;
        const int pbase = tokp ? (__ldg(&tokp[b]) * G4H) : 0;
        float g4[4];
#pragma unroll
        for (int g = 0; g < 4; g++)
            g4[g] = __ldg(&pre[pbase + (g << 9) + hhbase + hh]) + Gs[(g * 4 + hh) * 128 + b];
        const float cn = sigmoidf_(g4[1]) * csm[cell] + sigmoidf_(g4[0]) * tanhf(g4[2]);
        const float h = sigmoidf_(g4[3]) * tanhf(cn);
        csm[cell] = cn;
        hoT[(size_t)(hhbase + hh) * 128 + b] = h;
        if (hN) hN[(size_t)b * 512 + hhbase + hh] = h;
    }
    __syncthreads();
}

// ---------------- attention + output projection (block = batch row) ----------------
__device__ void attn_phase2(float* sm, int b, const int* lens, const float* phi_b,
    const float* out_w, const float* out_b,
    float* attn_out, float* logits_out)
{
    float* h2s  = sm;            // 512
    float* qs   = sm + 512;      // 128
    float* qp   = sm + 640;      // 1024
    float* as   = sm + 1664;     // 512
    float* ctxp = sm + 2176;     // 1024
    float* ctxs = sm + 3200;     // 128
    float* red  = sm + 3328;     // 256

    const int tid = threadIdx.x;
    const int warp = tid >> 5, lane = tid & 31;

    h2s[tid]       = __ldcg(&g_h2n[(size_t)b * 512 + tid]);
    h2s[tid + 256] = __ldcg(&g_h2n[(size_t)b * 512 + tid + 256]);
    __syncthreads();

    // q partials
    {
        float4 acc = make_float4(0.f, 0.f, 0.f, 0.f);
        for (int kk = 0; kk < 64; kk++) {
            int k = warp * 64 + kk;
            float hv = h2s[k];
            float4 pv = *reinterpret_cast<const float4*>(&g_phiT[(k << 7) + lane * 4]);
            acc.x = fmaf(hv, pv.x, acc.x); acc.y = fmaf(hv, pv.y, acc.y);
            acc.z = fmaf(hv, pv.z, acc.z); acc.w = fmaf(hv, pv.w, acc.w);
        }
        *reinterpret_cast<float4*>(&qp[warp * 128 + lane * 4]) = acc;
    }
    __syncthreads();
    if (tid < 128) {
        float q = phi_b[tid];
#pragma unroll
        for (int w = 0; w < 8; w++) q += qp[w * 128 + tid];
        qs[tid] = q;
    }
    __syncthreads();

    // energies
    {
        int half = tid >> 7, tl = tid & 127, l0 = tl * 4;
        float e0 = 0.f, e1 = 0.f, e2 = 0.f, e3 = 0.f;
        const float* kf = g_keyfT + ((size_t)b << 16) + l0;
        int c0 = half * 64;
#pragma unroll 4
        for (int c = c0; c < c0 + 64; c++) {
            float4 kv = __ldcg(reinterpret_cast<const float4*>(kf + ((size_t)c << 9)));
            float q = qs[c];
            e0 = fmaf(kv.x, q, e0); e1 = fmaf(kv.y, q, e1);
            e2 = fmaf(kv.z, q, e2); e3 = fmaf(kv.w, q, e3);
        }
        __syncthreads();
        *reinterpret_cast<float4*>(&qp[half * 512 + l0]) = make_float4(e0, e1, e2, e3);
    }
    __syncthreads();

    float e0 = qp[tid]       + qp[512 + tid];
    float e1 = qp[tid + 256] + qp[512 + tid + 256];

    red[tid] = fmaxf(e0, e1);
    __syncthreads();
    for (int s = 128; s > 0; s >>= 1) {
        if (tid < s) red[tid] = fmaxf(red[tid], red[tid + s]);
        __syncthreads();
    }
    const float mx = red[0];
    __syncthreads();

    const int len = lens[b];
    float p0 = (tid < len)       ? expf(e0 - mx) : 0.f;
    float p1 = (tid + 256 < len) ? expf(e1 - mx) : 0.f;
    red[tid] = p0 + p1;
    __syncthreads();
    for (int s = 128; s > 0; s >>= 1) {
        if (tid < s) red[tid] += red[tid + s];
        __syncthreads();
    }
    const float inv = 1.f / fmaxf(red[0], 1e-12f);
    __syncthreads();

    float av0 = p0 * inv, av1 = p1 * inv;
    as[tid] = av0; as[tid + 256] = av1;
    if (attn_out) {
        attn_out[(size_t)b * LL + tid]       = av0;
        attn_out[(size_t)b * LL + tid + 256] = av1;
    }
    __syncthreads();

    // ctx partials
    {
        float c0v = 0.f, c1v = 0.f, c2v = 0.f, c3v = 0.f;
        const float* vf = g_valf + ((size_t)b << 16) + lane * 4;
        for (int i = 0; i < 64; i++) {
            int l = warp * 64 + i;
            float4 vv = __ldcg(reinterpret_cast<const float4*>(vf + ((size_t)l << 7)));
            float av = as[l];
            c0v = fmaf(vv.x, av, c0v); c1v = fmaf(vv.y, av, c1v);
            c2v = fmaf(vv.z, av, c2v); c3v = fmaf(vv.w, av, c3v);
        }
        *reinterpret_cast<float4*>(&ctxp[warp * 128 + lane * 4]) = make_float4(c0v, c1v, c2v, c3v);
    }
    __syncthreads();
    if (tid < 128) {
        float c = 0.f;
#pragma unroll
        for (int w = 0; w < 8; w++) c += ctxp[w * 128 + tid];
        ctxs[tid] = c;
        g_ctxT[tid * 128 + b] = c;
    }
    __syncthreads();

    if (logits_out) {
        for (int v = warp; v < VV; v += 8) {
            const float* wr = out_w + (size_t)v * (HH + CC);
            float acc = 0.f;
#pragma unroll
            for (int it = 0; it < 5; it++) {
                int k0 = it * 128 + lane * 4;
                float4 wv = *reinterpret_cast<const float4*>(&wr[k0]);
                float4 xv = (it < 4) ? *reinterpret_cast<const float4*>(&h2s[k0])
                                     : *reinterpret_cast<const float4*>(&ctxs[k0 - 512]);
                acc = fmaf(wv.x, xv.x, acc); acc = fmaf(wv.y, xv.y, acc);
                acc = fmaf(wv.z, xv.z, acc); acc = fmaf(wv.w, xv.w, acc);
            }
#pragma unroll
            for (int off = 16; off > 0; off >>= 1)
                acc += __shfl_xor_sync(0xFFFFFFFF, acc, off);
            if (lane == 0) logits_out[(size_t)b * VV + v] = acc + out_b[v];
        }
    }
    __syncthreads();
}

// ---------------- persistent kernel ----------------
__global__ void __launch_bounds__(256, 1) speller_persistent(
    const int* __restrict__ lens, const float* __restrict__ phi_b,
    const float* __restrict__ out_w, const float* __restrict__ out_b,
    const float* __restrict__ cx0, const float* __restrict__ cx1,
    const float* __restrict__ cx2,
    float* __restrict__ attn_base, float* __restrict__ logits_base)
{
    __shared__ float Gs[16 * 128];
    __shared__ float csm[3 * 512];
    __shared__ float abuf[3584];

    const int bk = blockIdx.x;
    const int hhbase = bk * 4;
    const int tid = threadIdx.x;
    unsigned tgt = NBLK;

    for (int cell = tid; cell < 512; cell += 256) {
        int hh = cell >> 7;
        csm[cell]        = cx0[hhbase + hh];
        csm[512 + cell]  = cx1[hhbase + hh];
        csm[1024 + cell] = cx2[hhbase + hh];
    }
    __syncthreads();

    // initial context from initial decoder state
    attn_phase2(abuf, bk, lens, phi_b, out_w, out_b, nullptr, nullptr);
    gbar(tgt);

    const float* w0 = g_w0hl + (size_t)bk * 640 * 32;
    const float* w1 = g_w1hl + (size_t)bk * 1024 * 32;
    const float* w2 = g_w2hl + (size_t)bk * 1024 * 32;

    for (int t = 0; t < TT; t++) {
        const int p = t & 1;
        lstm_phase3(Gs, csm, hhbase,
                    g_ctxT, 16, g_h0T[p], 64,
                    w0, g_embW, g_tok + (size_t)t * BB,
                    g_h0T[p ^ 1], nullptr);
        gbar(tgt);
        lstm_phase3(Gs, csm + 512, hhbase,
                    g_h0T[p ^ 1], 64, g_h1T[p], 64,
                    w1, g_bias1, nullptr,
                    g_h1T[p ^ 1], nullptr);
        gbar(tgt);
        lstm_phase3(Gs, csm + 1024, hhbase,
                    g_h1T[p ^ 1], 64, g_h2T[p], 64,
                    w2, g_bias2, nullptr,
                    g_h2T[p ^ 1], g_h2n);
        gbar(tgt);
        attn_phase2(abuf, bk, lens, phi_b, out_w, out_b,
                    attn_base + (size_t)t * BB * LL,
                    logits_base + (size_t)t * BB * VV);
        gbar(tgt);
    }
}

// ---------------- precompute: W hi/lo split, per-block layout ----------------
__global__ void __launch_bounds__(256) whl_kernel(
    const float* __restrict__ wih0, const float* __restrict__ whh0,
    const float* __restrict__ wih1, const float* __restrict__ whh1,
    const float* __restrict__ wih2, const float* __restrict__ whh2)
{
    const int blk = blockIdx.x;
    const int tid = threadIdx.x;

    // layer 0: K=640 (ctx 128 | h 512)
    for (int i = tid; i < 640 * 16; i += 256) {
        int k = i >> 4, r = i & 15;
        int jrow = ((r >> 2) << 9) + blk * 4 + (r & 3);
        float v = (k < 128) ? wih0[(size_t)jrow * (EE + CC) + EE + k]
                            : whh0[(size_t)jrow * 512 + (k - 128)];
        unsigned h, l; tsplit(v, h, l);
        size_t o = ((size_t)blk * 640 * 16 + i) * 2;
        g_w0hl[o] = __uint_as_float(h); g_w0hl[o + 1] = __uint_as_float(l);
    }
    // layer 1: K=1024 (h0 512 | h1 512)
    for (int i = tid; i < 1024 * 16; i += 256) {
        int k = i >> 4, r = i & 15;
        int jrow = ((r >> 2) << 9) + blk * 4 + (r & 3);
        float v = (k < 512) ? wih1[(size_t)jrow * 512 + k]
                            : whh1[(size_t)jrow * 512 + (k - 512)];
        unsigned h, l; tsplit(v, h, l);
        size_t o = ((size_t)blk * 1024 * 16 + i) * 2;
        g_w1hl[o] = __uint_as_float(h); g_w1hl[o + 1] = __uint_as_float(l);
    }
    // layer 2
    for (int i = tid; i < 1024 * 16; i += 256) {
        int k = i >> 4, r = i & 15;
        int jrow = ((r >> 2) << 9) + blk * 4 + (r & 3);
        float v = (k < 512) ? wih2[(size_t)jrow * 512 + k]
                            : whh2[(size_t)jrow * 512 + (k - 512)];
        unsigned h, l; tsplit(v, h, l);
        size_t o = ((size_t)blk * 1024 * 16 + i) * 2;
        g_w2hl[o] = __uint_as_float(h); g_w2hl[o + 1] = __uint_as_float(l);
    }
}

// ---------------- precompute: keyf(T)/valf ----------------
__global__ void __launch_bounds__(256) keyval_kernel(
    const float* __restrict__ lf,
    const float* __restrict__ key_w, const float* __restrict__ key_b,
    const float* __restrict__ value_w, const float* __restrict__ value_b)
{
    __shared__ __align__(16) float As[16][64];
    __shared__ __align__(16) float Bs[16][64];

    const int tid = threadIdx.x;
    const int m0 = blockIdx.x * 64;
    const int n0 = blockIdx.y * 64;
    const int ty = tid >> 4;
    const int tx = tid & 15;

    float acc[4][4];
#pragma unroll
    for (int i = 0; i < 4; i++)
#pragma unroll
        for (int j = 0; j < 4; j++) acc[i][j] = 0.f;

    const int mi = tid >> 2;
    const int kq = (tid & 3) * 4;

    for (int kb = 0; kb < DD; kb += 16) {
        {
            float4 v = *reinterpret_cast<const float4*>(&lf[(size_t)(m0 + mi) * DD + kb + kq]);
            As[kq + 0][mi] = v.x; As[kq + 1][mi] = v.y; As[kq + 2][mi] = v.z; As[kq + 3][mi] = v.w;
        }
        {
            int n = n0 + mi;
            const float* wrow = (n < CC) ? (key_w + (size_t)n * DD) : (value_w + (size_t)(n - CC) * DD);
            float4 v = *reinterpret_cast<const float4*>(&wrow[kb + kq]);
            Bs[kq + 0][mi] = v.x; Bs[kq + 1][mi] = v.y; Bs[kq + 2][mi] = v.z; Bs[kq + 3][mi] = v.w;
        }
        __syncthreads();
#pragma unroll
        for (int k = 0; k < 16; k++) {
            float4 av = *reinterpret_cast<const float4*>(&As[k][ty * 4]);
            float4 bv = *reinterpret_cast<const float4*>(&Bs[k][tx * 4]);
            float aa[4] = {av.x, av.y, av.z, av.w};
            float bb[4] = {bv.x, bv.y, bv.z, bv.w};
#pragma unroll
            for (int i = 0; i < 4; i++)
#pragma unroll
                for (int j = 0; j < 4; j++) acc[i][j] = fmaf(aa[i], bb[j], acc[i][j]);
        }
        __syncthreads();
    }

#pragma unroll
    for (int i = 0; i < 4; i++) {
        int m = m0 + ty * 4 + i;
        int l = m >> 7, b = m & 127;
#pragma unroll
        for (int j = 0; j < 4; j++) {
            int n = n0 + tx * 4 + j;
            if (n < CC)
                g_keyfT[((size_t)b << 16) + (size_t)n * 512 + l] = acc[i][j] + key_b[n];
            else
                g_valf[((size_t)b << 16) + (size_t)l * CC + (n - CC)] = acc[i][j] + value_b[n - CC];
        }
    }
}

// ---------------- precompute: embW ----------------
__global__ void __launch_bounds__(256) embw_kernel(
    const float* __restrict__ emb, const float* __restrict__ w_ih0,
    const float* __restrict__ b_ih0, const float* __restrict__ b_hh0)
{
    __shared__ float es[EE];
    const int v = blockIdx.x, tid = threadIdx.x;
    for (int i = tid; i < EE; i += 256) es[i] = emb[(size_t)v * EE + i];
    __syncthreads();
    for (int j = tid; j < G4H; j += 256) {
        const float* wr = w_ih0 + (size_t)j * (EE + CC);
        float a0 = b_ih0[j] + b_hh0[j], a1 = 0.f, a2 = 0.f, a3 = 0.f;
        for (int e = 0; e < EE; e += 4) {
            a0 = fmaf(es[e + 0], wr[e + 0], a0);
            a1 = fmaf(es[e + 1], wr[e + 1], a1);
            a2 = fmaf(es[e + 2], wr[e + 2], a2);
            a3 = fmaf(es[e + 3], wr[e + 3], a3);
        }
        g_embW[(size_t)v * G4H + j] = a0 + a1 + a2 + a3;
    }
}

// ---------------- precompute: misc (fused) ----------------
__global__ void __launch_bounds__(256) misc_kernel(
    const float* __restrict__ bi1, const float* __restrict__ bh1,
    const float* __restrict__ bi2, const float* __restrict__ bh2,
    const float* __restrict__ phi_w, const int* __restrict__ transcript,
    const float* __restrict__ hx0, const float* __restrict__ hx1,
    const float* __restrict__ hx2)
{
    int i = blockIdx.x * 256 + threadIdx.x;
    if (i == 0) g_barctr = 0;
    if (i < G4H) { g_bias1[i] = bi1[i] + bh1[i]; g_bias2[i] = bi2[i] + bh2[i]; }
    if (i < HH * CC) {
        int k = i >> 7, c = i & 127;
        g_phiT[i] = phi_w[(size_t)c * HH + k];
    }
    if (i < TT * BB) {
        int t = i / BB, b = i % BB;
        g_tok[i] = (t == 0) ? 0 : transcript[(size_t)(t - 1) * BB + b];
    }
    if (i < HH * BB) {
        int k = i >> 7, b = i & 127;
        g_h0T[0][i] = hx0[k];
        g_h1T[0][i] = hx1[k];
        g_h2T[0][i] = hx2[k];
        g_h2n[(size_t)b * HH + k] = hx2[k];
    }
}

// ---------------- launch ----------------
extern "C" void kernel_launch(void* const* d_in, const int* in_sizes, int n_in,
                              void* d_out, int out_size)
{
    const float* lf         = (const float*)d_in[0];
    const int*   lens       = (const int*)  d_in[1];
    const int*   transcript = (const int*)  d_in[2];
    const float* emb        = (const float*)d_in[3];
    const float* w_ih0 = (const float*)d_in[4];
    const float* w_hh0 = (const float*)d_in[5];
    const float* b_ih0 = (const float*)d_in[6];
    const float* b_hh0 = (const float*)d_in[7];
    const float* w_ih1 = (const float*)d_in[8];
    const float* w_hh1 = (const float*)d_in[9];
    const float* b_ih1 = (const float*)d_in[10];
    const float* b_hh1 = (const float*)d_in[11];
    const float* w_ih2 = (const float*)d_in[12];
    const float* w_hh2 = (const float*)d_in[13];
    const float* b_ih2 = (const float*)d_in[14];
    const float* b_hh2 = (const float*)d_in[15];
    const float* phi_w = (const float*)d_in[16];
    const float* phi_b = (const float*)d_in[17];
    const float* key_w = (const float*)d_in[18];
    const float* key_b = (const float*)d_in[19];
    const float* value_w = (const float*)d_in[20];
    const float* value_b = (const float*)d_in[21];
    const float* out_w = (const float*)d_in[22];
    const float* out_b = (const float*)d_in[23];
    const float* hx0 = (const float*)d_in[24];
    const float* cx0 = (const float*)d_in[25];
    const float* hx1 = (const float*)d_in[26];
    const float* cx1 = (const float*)d_in[27];
    const float* hx2 = (const float*)d_in[28];
    const float* cx2 = (const float*)d_in[29];

    float* out = (float*)d_out;
    float* logits_base = out;                        // [T,B,V]
    float* attn_base   = out + (size_t)TT * BB * VV; // [T,B,L]

    keyval_kernel<<<dim3(1024, 4), 256>>>(lf, key_w, key_b, value_w, value_b);
    embw_kernel<<<VV, 256>>>(emb, w_ih0, b_ih0, b_hh0);
    whl_kernel<<<NBLK, 256>>>(w_ih0, w_hh0, w_ih1, w_hh1, w_ih2, w_hh2);
    misc_kernel<<<256, 256>>>(b_ih1, b_hh1, b_ih2, b_hh2, phi_w, transcript,
                              hx0, hx1, hx2);
    speller_persistent<<<NBLK, 256>>>(lens, phi_b, out_w, out_b,
                                      cx0, cx1, cx2,
                                      attn_base, logits_base);
}

// round 6
// speedup vs baseline: 1.2061x; 1.1792x over previous
#include <cuda_runtime.h>
#include <math.h>

#define LL 512
#define BB 128
#define DD 512
#define TT 200
#define EE 384
#define CC 128
#define HH 512
#define VV 46
#define G4H 2048
#define NBLK 128

// k8 counts: L0=80 (K=640), L1=128, L2=128
#define NK8_L0 80
#define NK8_L1 128
#define NK8_L2 128
#define NK8_TOT 336
#define WFRAG_PER_BLK (NK8_TOT * 256)   // 336 k8 * 32 lanes * 8 floats

// smem layout (floats)
#define XS_OFF 0            // 3 * 32*136 = 13056
#define XBUF   4352
#define WS_OFF 13056        // 3 * 1024 = 3072
#define GS_OFF 16128        // 2048
#define CS_OFF 18176        // 1536
#define SMEM_FLOATS 19712

// ---------------- device scratch ----------------
__device__ __align__(128) float g_keyfT[BB * CC * LL];  // [b][c][l]
__device__ __align__(128) float g_valf[BB * LL * CC];   // [b][l][c]
__device__ __align__(128) float g_embW[VV * G4H];
__device__ __align__(128) float g_bias1[G4H];
__device__ __align__(128) float g_bias2[G4H];
__device__ __align__(128) float g_h0T[2][HH * BB];      // [k][b]
__device__ __align__(128) float g_h1T[2][HH * BB];
__device__ __align__(128) float g_h2T[2][HH * BB];
__device__ __align__(128) float g_h2n[BB * HH];         // [b][k]
__device__ __align__(128) float g_ctxT[CC * BB];        // [c][b]
__device__ __align__(128) float g_phiT[HH * CC];        // [k][c]
__device__ __align__(128) float g_wfrag[NBLK * WFRAG_PER_BLK];  // fragment-ordered W hi/lo
__device__ int   g_tok[TT * BB];
__device__ unsigned g_barctr;

__device__ __forceinline__ float sigmoidf_(float x) { return 1.f / (1.f + expf(-x)); }

// tf32 split: x = hi + lo
__device__ __forceinline__ void tsplit(float x, unsigned& h, unsigned& l) {
    asm("cvt.rna.tf32.f32 %0, %1;" : "=r"(h) : "f"(x));
    float r = x - __uint_as_float(h);
    asm("cvt.rna.tf32.f32 %0, %1;" : "=r"(l) : "f"(r));
}

__device__ __forceinline__ void mma8(float c[4],
    unsigned a0, unsigned a1, unsigned a2, unsigned a3,
    unsigned b0, unsigned b1)
{
    asm volatile("mma.sync.aligned.m16n8k8.row.col.f32.tf32.tf32.f32 "
        "{%0,%1,%2,%3}, {%4,%5,%6,%7}, {%8,%9}, {%0,%1,%2,%3};"
        : "+f"(c[0]), "+f"(c[1]), "+f"(c[2]), "+f"(c[3])
        : "r"(a0), "r"(a1), "r"(a2), "r"(a3), "r"(b0), "r"(b1));
}

// ---------------- grid barrier ----------------
__device__ __forceinline__ void gbar(unsigned& tgt) {
    __threadfence();
    __syncthreads();
    if (threadIdx.x == 0) {
        atomicAdd(&g_barctr, 1u);
        unsigned v;
        do {
            asm volatile("ld.acquire.gpu.u32 %0, [%1];" : "=r"(v) : "l"(&g_barctr) : "memory");
        } while (v < tgt);
    }
    __syncthreads();
    tgt += NBLK;
}

// ---------------- cp.async ----------------
__device__ __forceinline__ void cp_cg16(float* dst, const float* src) {
    unsigned d = (unsigned)__cvta_generic_to_shared(dst);
    asm volatile("cp.async.cg.shared.global [%0], [%1], 16;" :: "r"(d), "l"(src) : "memory");
}
__device__ __forceinline__ void cp_ca16(float* dst, const float* src) {
    unsigned d = (unsigned)__cvta_generic_to_shared(dst);
    asm volatile("cp.async.ca.shared.global [%0], [%1], 16;" :: "r"(d), "l"(src) : "memory");
}

// stage chunk c (32 k-rows of X, 4 k8 of W) into buffer buf
__device__ __forceinline__ void stage_chunk(float* Xs, float* Wsm, int c, int buf,
    const float* xa, int KA, const float* xh, const float* wfrag)
{
    const int tid = threadIdx.x;
#pragma unroll
    for (int i = 0; i < 2; i++) {
        int idx = tid + i * 512;              // 0..1023
        int row = idx >> 5;                   // 0..31
        int off = (idx & 31) << 2;            // 0..124
        int k = c * 32 + row;
        const float* src = (k < KA) ? (xa + (size_t)k * 128 + off)
                                    : (xh + (size_t)(k - KA) * 128 + off);
        cp_cg16(Xs + buf * XBUF + row * 136 + off, src);
    }
    if (tid < 256)
        cp_ca16(Wsm + buf * 1024 + tid * 4, wfrag + (size_t)c * 1024 + tid * 4);
    asm volatile("cp.async.commit_group;" ::: "memory");
}

// ---------------- LSTM phase (tensor core, smem-fed) ----------------
__device__ void lstm_tc(float* smem, int hhbase,
    const float* xa, int KA, const float* xh, int K,
    const float* wfrag, const float* pre, const int* tokp,
    float* hoT, float* csm, float* hN)
{
    float* Xs  = smem + XS_OFF;
    float* Wsm = smem + WS_OFF;
    float* Gs  = smem + GS_OFF;

    const int tid = threadIdx.x;
    const int w = tid >> 5, lane = tid & 31;
    const int g = lane >> 2, q = lane & 3;
    const int nch = K >> 5;

    float cA[4] = {0.f, 0.f, 0.f, 0.f};
    float cB[4] = {0.f, 0.f, 0.f, 0.f};

    stage_chunk(Xs, Wsm, 0, 0, xa, KA, xh, wfrag);
    stage_chunk(Xs, Wsm, 1, 1, xa, KA, xh, wfrag);

    for (int c = 0; c < nch; c++) {
        if (c + 1 < nch) asm volatile("cp.async.wait_group 1;" ::: "memory");
        else             asm volatile("cp.async.wait_group 0;" ::: "memory");
        __syncthreads();
        if (c + 2 < nch) {
            int nb = c + 2; int bi = nb - (nb / 3) * 3;
            stage_chunk(Xs, Wsm, nb, bi, xa, KA, xh, wfrag);
        }
        const int cb = c - (c / 3) * 3;
        const float* Xb = Xs + cb * XBUF;
        const float* Wb = Wsm + cb * 1024;
#pragma unroll
        for (int j = 0; j < 4; j++) {
            float4 w1 = *reinterpret_cast<const float4*>(Wb + j * 256 + lane * 8);
            float4 w2 = *reinterpret_cast<const float4*>(Wb + j * 256 + lane * 8 + 4);
            float x0 = Xb[(j * 8 + q) * 136 + w * 8 + g];
            float x1 = Xb[(j * 8 + q + 4) * 136 + w * 8 + g];
            unsigned bh0, bl0, bh1, bl1;
            tsplit(x0, bh0, bl0);
            tsplit(x1, bh1, bl1);
            mma8(cA, __float_as_uint(w1.x), __float_as_uint(w1.z),
                     __float_as_uint(w2.x), __float_as_uint(w2.z), bh0, bh1);
            mma8(cB, __float_as_uint(w1.x), __float_as_uint(w1.z),
                     __float_as_uint(w2.x), __float_as_uint(w2.z), bl0, bl1);
            mma8(cA, __float_as_uint(w1.y), __float_as_uint(w1.w),
                     __float_as_uint(w2.y), __float_as_uint(w2.w), bh0, bh1);
        }
    }

    // writeback C fragments: rows = gate cols (m), cols = batches (n)
    Gs[g * 128 + w * 8 + 2 * q]             = cA[0] + cB[0];
    Gs[g * 128 + w * 8 + 2 * q + 1]         = cA[1] + cB[1];
    Gs[(g + 8) * 128 + w * 8 + 2 * q]       = cA[2] + cB[2];
    Gs[(g + 8) * 128 + w * 8 + 2 * q + 1]   = cA[3] + cB[3];
    __syncthreads();

    // fused bias + nonlinearity: 1 cell per thread
    {
        const int hh = tid >> 7, b = tid & 127;
        const int pbase = tokp ? (__ldg(&tokp[b]) * G4H) : 0;
        float g4[4];
#pragma unroll
        for (int gg = 0; gg < 4; gg++)
            g4[gg] = __ldg(&pre[pbase + (gg << 9) + hhbase + hh]) + Gs[(gg * 4 + hh) * 128 + b];
        const float cn = sigmoidf_(g4[1]) * csm[tid] + sigmoidf_(g4[0]) * tanhf(g4[2]);
        const float h = sigmoidf_(g4[3]) * tanhf(cn);
        csm[tid] = cn;
        hoT[(size_t)(hhbase + hh) * 128 + b] = h;
        if (hN) hN[(size_t)b * 512 + hhbase + hh] = h;
    }
}

// ---------------- attention + output projection (512 threads, block = batch row) ----------------
__device__ void attn5(float* sm, int b, const int* lens, const float* phi_b,
    const float* out_w, const float* out_b,
    float* attn_out, float* logits_out)
{
    float* h2s  = sm;            // 512
    float* qs   = sm + 512;      // 128
    float* part = sm + 640;      // 2048 (16x128)
    float* as   = sm + 2688;     // 512
    float* ctxs = sm + 3200;     // 128
    float* red  = sm + 3328;     // 512

    const int tid = threadIdx.x;
    const int warp = tid >> 5, lane = tid & 31;

    h2s[tid] = __ldcg(&g_h2n[(size_t)b * 512 + tid]);
    __syncthreads();

    // q partials: warp w -> k slice [32w, 32w+32), lane -> 4 c's
    {
        float4 acc = make_float4(0.f, 0.f, 0.f, 0.f);
#pragma unroll 8
        for (int kk = 0; kk < 32; kk++) {
            int k = warp * 32 + kk;
            float hv = h2s[k];
            float4 pv = *reinterpret_cast<const float4*>(&g_phiT[(k << 7) + lane * 4]);
            acc.x = fmaf(hv, pv.x, acc.x); acc.y = fmaf(hv, pv.y, acc.y);
            acc.z = fmaf(hv, pv.z, acc.z); acc.w = fmaf(hv, pv.w, acc.w);
        }
        *reinterpret_cast<float4*>(&part[warp * 128 + lane * 4]) = acc;
    }
    __syncthreads();
    if (tid < 128) {
        float qv = phi_b[tid];
#pragma unroll
        for (int w = 0; w < 16; w++) qv += part[w * 128 + tid];
        qs[tid] = qv;
    }
    __syncthreads();

    // energies: 1 frame per thread
    float e = 0.f;
    {
        const float* kf = g_keyfT + ((size_t)b << 16) + tid;
        float a0 = 0.f, a1 = 0.f, a2 = 0.f, a3 = 0.f;
#pragma unroll 8
        for (int c = 0; c < 128; c += 4) {
            a0 = fmaf(__ldcg(kf + ((size_t)(c + 0) << 9)), qs[c + 0], a0);
            a1 = fmaf(__ldcg(kf + ((size_t)(c + 1) << 9)), qs[c + 1], a1);
            a2 = fmaf(__ldcg(kf + ((size_t)(c + 2) << 9)), qs[c + 2], a2);
            a3 = fmaf(__ldcg(kf + ((size_t)(c + 3) << 9)), qs[c + 3], a3);
        }
        e = (a0 + a1) + (a2 + a3);
    }

    red[tid] = e;
    __syncthreads();
    for (int s = 256; s > 0; s >>= 1) {
        if (tid < s) red[tid] = fmaxf(red[tid], red[tid + s]);
        __syncthreads();
    }
    const float mx = red[0];
    __syncthreads();

    const int len = lens[b];
    float p = (tid < len) ? expf(e - mx) : 0.f;
    red[tid] = p;
    __syncthreads();
    for (int s = 256; s > 0; s >>= 1) {
        if (tid < s) red[tid] += red[tid + s];
        __syncthreads();
    }
    const float inv = 1.f / fmaxf(red[0], 1e-12f);
    __syncthreads();

    const float av = p * inv;
    as[tid] = av;
    if (attn_out) attn_out[(size_t)b * LL + tid] = av;
    __syncthreads();

    // ctx partials: warp w -> l slice [32w, 32w+32), lane -> 4 c's
    {
        float4 acc = make_float4(0.f, 0.f, 0.f, 0.f);
        const float* vf = g_valf + ((size_t)b << 16) + lane * 4;
#pragma unroll 8
        for (int i = 0; i < 32; i++) {
            int l = warp * 32 + i;
            float4 vv = __ldcg(reinterpret_cast<const float4*>(vf + ((size_t)l << 7)));
            float a_ = as[l];
            acc.x = fmaf(vv.x, a_, acc.x); acc.y = fmaf(vv.y, a_, acc.y);
            acc.z = fmaf(vv.z, a_, acc.z); acc.w = fmaf(vv.w, a_, acc.w);
        }
        *reinterpret_cast<float4*>(&part[warp * 128 + lane * 4]) = acc;
    }
    __syncthreads();
    if (tid < 128) {
        float cv = 0.f;
#pragma unroll
        for (int w = 0; w < 16; w++) cv += part[w * 128 + tid];
        ctxs[tid] = cv;
        g_ctxT[tid * 128 + b] = cv;
    }
    __syncthreads();

    if (logits_out) {
        for (int v = warp; v < VV; v += 16) {
            const float* wr = out_w + (size_t)v * (HH + CC);
            float acc = 0.f;
#pragma unroll
            for (int it = 0; it < 5; it++) {
                int k0 = it * 128 + lane * 4;
                float4 wv = *reinterpret_cast<const float4*>(&wr[k0]);
                float4 xv = (it < 4) ? *reinterpret_cast<const float4*>(&h2s[k0])
                                     : *reinterpret_cast<const float4*>(&ctxs[k0 - 512]);
                acc = fmaf(wv.x, xv.x, acc); acc = fmaf(wv.y, xv.y, acc);
                acc = fmaf(wv.z, xv.z, acc); acc = fmaf(wv.w, xv.w, acc);
            }
#pragma unroll
            for (int off = 16; off > 0; off >>= 1)
                acc += __shfl_xor_sync(0xFFFFFFFF, acc, off);
            if (lane == 0) logits_out[(size_t)b * VV + v] = acc + out_b[v];
        }
    }
    __syncthreads();
}

// ---------------- persistent kernel ----------------
__global__ void __launch_bounds__(512, 1) speller_persistent(
    const int* __restrict__ lens, const float* __restrict__ phi_b,
    const float* __restrict__ out_w, const float* __restrict__ out_b,
    const float* __restrict__ cx0, const float* __restrict__ cx1,
    const float* __restrict__ cx2,
    float* __restrict__ attn_base, float* __restrict__ logits_base)
{
    extern __shared__ float smem[];
    float* csm = smem + CS_OFF;

    const int bk = blockIdx.x;
    const int hhbase = bk * 4;
    const int tid = threadIdx.x;
    unsigned tgt = NBLK;

    {
        int hh = tid >> 7;
        csm[tid]        = cx0[hhbase + hh];
        csm[512 + tid]  = cx1[hhbase + hh];
        csm[1024 + tid] = cx2[hhbase + hh];
    }
    __syncthreads();

    attn5(smem, bk, lens, phi_b, out_w, out_b, nullptr, nullptr);
    gbar(tgt);

    const float* wf0 = g_wfrag + (size_t)bk * WFRAG_PER_BLK;
    const float* wf1 = wf0 + NK8_L0 * 256;
    const float* wf2 = wf1 + NK8_L1 * 256;

    for (int t = 0; t < TT; t++) {
        const int p = t & 1;
        lstm_tc(smem, hhbase, g_ctxT, 128, g_h0T[p], 640,
                wf0, g_embW, g_tok + (size_t)t * BB,
                g_h0T[p ^ 1], csm, nullptr);
        gbar(tgt);
        lstm_tc(smem, hhbase, g_h0T[p ^ 1], 512, g_h1T[p], 1024,
                wf1, g_bias1, nullptr,
                g_h1T[p ^ 1], csm + 512, nullptr);
        gbar(tgt);
        lstm_tc(smem, hhbase, g_h1T[p ^ 1], 512, g_h2T[p], 1024,
                wf2, g_bias2, nullptr,
                g_h2T[p ^ 1], csm + 1024, g_h2n);
        gbar(tgt);
        attn5(smem, bk, lens, phi_b, out_w, out_b,
              attn_base + (size_t)t * BB * LL,
              logits_base + (size_t)t * BB * VV);
        gbar(tgt);
    }
}

// ---------------- precompute: fragment-ordered tf32 hi/lo W ----------------
__global__ void __launch_bounds__(256) whl_kernel(
    const float* __restrict__ wih0, const float* __restrict__ whh0,
    const float* __restrict__ wih1, const float* __restrict__ whh1,
    const float* __restrict__ wih2, const float* __restrict__ whh2)
{
    const int blk = blockIdx.x;
    float* dst = g_wfrag + (size_t)blk * WFRAG_PER_BLK;

    for (int idx = threadIdx.x; idx < WFRAG_PER_BLK; idx += 256) {
        int j8 = idx >> 8;            // 0..335
        int rem = idx & 255;
        int lane = rem >> 3;
        int sel = rem & 7;
        int kq = lane & 3, bq = lane >> 2;
        int pr = sel >> 1, hilo = sel & 1;
        int col = bq + ((pr & 1) ? 8 : 0);
        int jrow = ((col >> 2) << 9) + blk * 4 + (col & 3);

        int layer, j;
        if (j8 < NK8_L0)              { layer = 0; j = j8; }
        else if (j8 < NK8_L0 + NK8_L1){ layer = 1; j = j8 - NK8_L0; }
        else                          { layer = 2; j = j8 - NK8_L0 - NK8_L1; }
        int kk = j * 8 + kq + ((pr >= 2) ? 4 : 0);

        float v;
        if (layer == 0)
            v = (kk < 128) ? wih0[(size_t)jrow * (EE + CC) + EE + kk]
                           : whh0[(size_t)jrow * 512 + kk - 128];
        else if (layer == 1)
            v = (kk < 512) ? wih1[(size_t)jrow * 512 + kk]
                           : whh1[(size_t)jrow * 512 + kk - 512];
        else
            v = (kk < 512) ? wih2[(size_t)jrow * 512 + kk]
                           : whh2[(size_t)jrow * 512 + kk - 512];

        unsigned h, l; tsplit(v, h, l);
        dst[idx] = __uint_as_float(hilo ? l : h);
    }
}

// ---------------- precompute: keyf(T)/valf ----------------
__global__ void __launch_bounds__(256) keyval_kernel(
    const float* __restrict__ lf,
    const float* __restrict__ key_w, const float* __restrict__ key_b,
    const float* __restrict__ value_w, const float* __restrict__ value_b)
{
    __shared__ __align__(16) float As[16][64];
    __shared__ __align__(16) float Bs[16][64];

    const int tid = threadIdx.x;
    const int m0 = blockIdx.x * 64;
    const int n0 = blockIdx.y * 64;
    const int ty = tid >> 4;
    const int tx = tid & 15;

    float acc[4][4];
#pragma unroll
    for (int i = 0; i < 4; i++)
#pragma unroll
        for (int j = 0; j < 4; j++) acc[i][j] = 0.f;

    const int mi = tid >> 2;
    const int kq = (tid & 3) * 4;

    for (int kb = 0; kb < DD; kb += 16) {
        {
            float4 v = *reinterpret_cast<const float4*>(&lf[(size_t)(m0 + mi) * DD + kb + kq]);
            As[kq + 0][mi] = v.x; As[kq + 1][mi] = v.y; As[kq + 2][mi] = v.z; As[kq + 3][mi] = v.w;
        }
        {
            int n = n0 + mi;
            const float* wrow = (n < CC) ? (key_w + (size_t)n * DD) : (value_w + (size_t)(n - CC) * DD);
            float4 v = *reinterpret_cast<const float4*>(&wrow[kb + kq]);
            Bs[kq + 0][mi] = v.x; Bs[kq + 1][mi] = v.y; Bs[kq + 2][mi] = v.z; Bs[kq + 3][mi] = v.w;
        }
        __syncthreads();
#pragma unroll
        for (int k = 0; k < 16; k++) {
            float4 av = *reinterpret_cast<const float4*>(&As[k][ty * 4]);
            float4 bv = *reinterpret_cast<const float4*>(&Bs[k][tx * 4]);
            float aa[4] = {av.x, av.y, av.z, av.w};
            float bb[4] = {bv.x, bv.y, bv.z, bv.w};
#pragma unroll
            for (int i = 0; i < 4; i++)
#pragma unroll
                for (int j = 0; j < 4; j++) acc[i][j] = fmaf(aa[i], bb[j], acc[i][j]);
        }
        __syncthreads();
    }

#pragma unroll
    for (int i = 0; i < 4; i++) {
        int m = m0 + ty * 4 + i;
        int l = m >> 7, b = m & 127;
#pragma unroll
        for (int j = 0; j < 4; j++) {
            int n = n0 + tx * 4 + j;
            if (n < CC)
                g_keyfT[((size_t)b << 16) + (size_t)n * 512 + l] = acc[i][j] + key_b[n];
            else
                g_valf[((size_t)b << 16) + (size_t)l * CC + (n - CC)] = acc[i][j] + value_b[n - CC];
        }
    }
}

// ---------------- precompute: embW ----------------
__global__ void __launch_bounds__(256) embw_kernel(
    const float* __restrict__ emb, const float* __restrict__ w_ih0,
    const float* __restrict__ b_ih0, const float* __restrict__ b_hh0)
{
    __shared__ float es[EE];
    const int v = blockIdx.x, tid = threadIdx.x;
    for (int i = tid; i < EE; i += 256) es[i] = emb[(size_t)v * EE + i];
    __syncthreads();
    for (int j = tid; j < G4H; j += 256) {
        const float* wr = w_ih0 + (size_t)j * (EE + CC);
        float a0 = b_ih0[j] + b_hh0[j], a1 = 0.f, a2 = 0.f, a3 = 0.f;
        for (int e = 0; e < EE; e += 4) {
            a0 = fmaf(es[e + 0], wr[e + 0], a0);
            a1 = fmaf(es[e + 1], wr[e + 1], a1);
            a2 = fmaf(es[e + 2], wr[e + 2], a2);
            a3 = fmaf(es[e + 3], wr[e + 3], a3);
        }
        g_embW[(size_t)v * G4H + j] = a0 + a1 + a2 + a3;
    }
}

// ---------------- precompute: misc ----------------
__global__ void __launch_bounds__(256) misc_kernel(
    const float* __restrict__ bi1, const float* __restrict__ bh1,
    const float* __restrict__ bi2, const float* __restrict__ bh2,
    const float* __restrict__ phi_w, const int* __restrict__ transcript,
    const float* __restrict__ hx0, const float* __restrict__ hx1,
    const float* __restrict__ hx2)
{
    int i = blockIdx.x * 256 + threadIdx.x;
    if (i == 0) g_barctr = 0;
    if (i < G4H) { g_bias1[i] = bi1[i] + bh1[i]; g_bias2[i] = bi2[i] + bh2[i]; }
    if (i < HH * CC) {
        int k = i >> 7, c = i & 127;
        g_phiT[i] = phi_w[(size_t)c * HH + k];
    }
    if (i < TT * BB) {
        int t = i / BB, b = i % BB;
        g_tok[i] = (t == 0) ? 0 : transcript[(size_t)(t - 1) * BB + b];
    }
    if (i < HH * BB) {
        int k = i >> 7, b = i & 127;
        g_h0T[0][i] = hx0[k];
        g_h1T[0][i] = hx1[k];
        g_h2T[0][i] = hx2[k];
        g_h2n[(size_t)b * HH + k] = hx2[k];
    }
}

// ---------------- launch ----------------
extern "C" void kernel_launch(void* const* d_in, const int* in_sizes, int n_in,
                              void* d_out, int out_size)
{
    const float* lf         = (const float*)d_in[0];
    const int*   lens       = (const int*)  d_in[1];
    const int*   transcript = (const int*)  d_in[2];
    const float* emb        = (const float*)d_in[3];
    const float* w_ih0 = (const float*)d_in[4];
    const float* w_hh0 = (const float*)d_in[5];
    const float* b_ih0 = (const float*)d_in[6];
    const float* b_hh0 = (const float*)d_in[7];
    const float* w_ih1 = (const float*)d_in[8];
    const float* w_hh1 = (const float*)d_in[9];
    const float* b_ih1 = (const float*)d_in[10];
    const float* b_hh1 = (const float*)d_in[11];
    const float* w_ih2 = (const float*)d_in[12];
    const float* w_hh2 = (const float*)d_in[13];
    const float* b_ih2 = (const float*)d_in[14];
    const float* b_hh2 = (const float*)d_in[15];
    const float* phi_w = (const float*)d_in[16];
    const float* phi_b = (const float*)d_in[17];
    const float* key_w = (const float*)d_in[18];
    const float* key_b = (const float*)d_in[19];
    const float* value_w = (const float*)d_in[20];
    const float* value_b = (const float*)d_in[21];
    const float* out_w = (const float*)d_in[22];
    const float* out_b = (const float*)d_in[23];
    const float* hx0 = (const float*)d_in[24];
    const float* cx0 = (const float*)d_in[25];
    const float* hx1 = (const float*)d_in[26];
    const float* cx1 = (const float*)d_in[27];
    const float* hx2 = (const float*)d_in[28];
    const float* cx2 = (const float*)d_in[29];

    float* out = (float*)d_out;
    float* logits_base = out;                        // [T,B,V]
    float* attn_base   = out + (size_t)TT * BB * VV; // [T,B,L]

    const int smem_bytes = SMEM_FLOATS * 4;
    cudaFuncSetAttribute(speller_persistent,
                         cudaFuncAttributeMaxDynamicSharedMemorySize, smem_bytes);

    keyval_kernel<<<dim3(1024, 4), 256>>>(lf, key_w, key_b, value_w, value_b);
    embw_kernel<<<VV, 256>>>(emb, w_ih0, b_ih0, b_hh0);
    whl_kernel<<<NBLK, 256>>>(w_ih0, w_hh0, w_ih1, w_hh1, w_ih2, w_hh2);
    misc_kernel<<<256, 256>>>(b_ih1, b_hh1, b_ih2, b_hh2, phi_w, transcript,
                              hx0, hx1, hx2);
    speller_persistent<<<NBLK, 512, smem_bytes>>>(
        lens, phi_b, out_w, out_b, cx0, cx1, cx2,
        attn_base, logits_base);
}